// round 13
// baseline (speedup 1.0000x reference)
#include <cuda_runtime.h>
#include <cuda_bf16.h>
#include <math.h>

// ============================================================================
// Bayesian LSTM forward:  B=8192, T=256, IN=1, H=10
// R10: R9 layout (1 lane per gate-row, 3 elems/warp, 2731 warps) but the h
//      broadcast moves from 10x SHFL to double-buffered SMEM:
//        - STS.64 of (h,h) per lane per step
//        - 5x LDS.128 -> ulonglong2 halves are ready (h,h) f32x2 operands
//        - zero pack-MOVs in the matvec, 1 __syncwarp per step
//      Group stride 224B => the 4 lane-groups are bank-disjoint on LDS.
// ============================================================================

#define HDIM   10
#define TSTEPS 256
#define BATCH  8192

using u64 = unsigned long long;

// ---------------- packed f32x2 helpers ----------------
__device__ __forceinline__ u64 pack2(float lo, float hi) {
    u64 r; asm("mov.b64 %0, {%1, %2};" : "=l"(r) : "f"(lo), "f"(hi)); return r;
}
__device__ __forceinline__ void unpack2(u64 v, float& lo, float& hi) {
    asm("mov.b64 {%0, %1}, %2;" : "=f"(lo), "=f"(hi) : "l"(v));
}
__device__ __forceinline__ u64 ffma2(u64 a, u64 b, u64 c) {
    u64 d; asm("fma.rn.f32x2 %0, %1, %2, %3;" : "=l"(d) : "l"(a), "l"(b), "l"(c)); return d;
}
__device__ __forceinline__ u64 fmul2(u64 a, u64 b) {
    u64 d; asm("mul.rn.f32x2 %0, %1, %2;" : "=l"(d) : "l"(a), "l"(b)); return d;
}
__device__ __forceinline__ u64 fadd2(u64 a, u64 b) {
    u64 d; asm("add.rn.f32x2 %0, %1, %2;" : "=l"(d) : "l"(a), "l"(b)); return d;
}
__device__ __forceinline__ float ex2a(float x) {
    float y; asm("ex2.approx.f32 %0, %1;" : "=f"(y) : "f"(x)); return y;
}
__device__ __forceinline__ float rcpa(float x) {
    float y; asm("rcp.approx.f32 %0, %1;" : "=f"(y) : "f"(x)); return y;
}

// ---------------- packed, prescaled sampled weights ----------------
// Per gate-row j (0..9), per hidden m (0..9):
//   g_wif[j][m] = ( K1*w_hh[m][ j],   K1*w_hh[m][10+j] )   (i,f)
//   g_wgo[j][m] = ( K2*w_hh[m][20+j], K1*w_hh[m][30+j] )   (g,o)
// K1 = -log2(e) (sigmoid), K2 = -2*log2(e) (tanh).
__device__ u64  g_wif[10][10];
__device__ u64  g_wgo[10][10];
__device__ u64  g_xif[10], g_xgo[10];   // w_ih
__device__ u64  g_bif[10], g_bgo[10];   // bias
__device__ float g_linw[HDIM];
__device__ float g_linb;

#define K1C (-1.44269504088896341f)
#define K2C (-2.88539008177792681f)

__global__ void sample_pack_kernel(
    const float* __restrict__ w_ih_mu, const float* __restrict__ w_ih_rho,
    const float* __restrict__ w_hh_mu, const float* __restrict__ w_hh_rho,
    const float* __restrict__ b_mu,    const float* __restrict__ b_rho,
    const float* __restrict__ eps_ih,  const float* __restrict__ eps_hh,
    const float* __restrict__ eps_b,
    const float* __restrict__ lin_w,   const float* __restrict__ lin_b)
{
    __shared__ float s_wih[40];
    __shared__ float s_b[40];
    __shared__ float s_whh[10][40];
    int t = threadIdx.x;

    for (int g = t; g < 40; g += blockDim.x) {
        s_wih[g] = w_ih_mu[g] + log1pf(expf(w_ih_rho[g])) * eps_ih[g];
        s_b[g]   = b_mu[g]    + log1pf(expf(b_rho[g]))    * eps_b[g];
    }
    for (int idx = t; idx < 400; idx += blockDim.x) {
        int m = idx / 40, g = idx % 40;
        s_whh[m][g] = w_hh_mu[idx] + log1pf(expf(w_hh_rho[idx])) * eps_hh[idx];
    }
    __syncthreads();

    for (int idx = t; idx < 100; idx += blockDim.x) {
        int j = idx / 10, m = idx % 10;
        g_wif[j][m] = pack2(K1C * s_whh[m][j],      K1C * s_whh[m][10 + j]);
        g_wgo[j][m] = pack2(K2C * s_whh[m][20 + j], K1C * s_whh[m][30 + j]);
    }
    if (t < 10) {
        int j = t;
        g_xif[j] = pack2(K1C * s_wih[j],      K1C * s_wih[10 + j]);
        g_xgo[j] = pack2(K2C * s_wih[20 + j], K1C * s_wih[30 + j]);
        g_bif[j] = pack2(K1C * s_b[j],        K1C * s_b[10 + j]);
        g_bgo[j] = pack2(K2C * s_b[20 + j],   K1C * s_b[30 + j]);
    }
    if (t < HDIM) g_linw[t] = lin_w[t];
    if (t == 0)   g_linb = lin_b[0];
}

// ---------------- main LSTM kernel ----------------
// 32-thread blocks; lanes [10g, 10g+10) handle batch element blockIdx.x*3+g.
// Lanes 30,31 are aliased onto a scratch smem group so they run the same code
// (needed for the full-mask __syncwarp) without corrupting real state.
//
// SMEM per block (1 warp): 4 groups x 224B. Each group: two 96B h-buffers
// (10 duplicated pairs = 80B, padded). Step parity selects read/write buffer.
__global__ void __launch_bounds__(32, 18) lstm_fwd_kernel(
    const float* __restrict__ x, float* __restrict__ out)
{
    __shared__ __align__(16) unsigned char sh[4 * 224 + 16];

    const int lane = threadIdx.x & 31;
    const bool idle = (lane >= 30);
    const int grp  = idle ? 2 : (lane / 10);      // batch-element group
    const int sgrp = idle ? 3 : grp;              // smem group (3 = scratch)
    const int row  = idle ? (lane - 30) : (lane - grp * 10);

    int elem = blockIdx.x * 3 + grp;
    const bool valid = !idle && (elem < BATCH);
    if (elem >= BATCH) elem = BATCH - 1;          // clamp for safe loads

    unsigned char* const gb   = sh + sgrp * 224;  // group base
    unsigned char* const bufA = gb;               // parity-0 buffer
    unsigned char* const bufB = gb + 96;          // parity-1 buffer

    // ---- weights into registers (20 u64 = 40 regs) ----
    u64 wif[10], wgo[10];
#pragma unroll
    for (int m = 0; m < 10; m++) {
        wif[m] = g_wif[row][m];
        wgo[m] = g_wgo[row][m];
    }
    const u64 xif = g_xif[row], xgo = g_xgo[row];
    const u64 bif = g_bif[row], bgo = g_bgo[row];

    float chat = 0.f;                             // chat = K2 * c

    // prefill parity-0 buffer with h = 0 pairs
    *reinterpret_cast<u64*>(bufA + 8 * row) = 0ull;
    __syncwarp();

    const float4* xp = reinterpret_cast<const float4*>(x + (size_t)elem * TSTEPS);

#pragma unroll 1
    for (int t4 = 0; t4 < TSTEPS / 4; t4++) {
        float4 xv = xp[t4];
        float xs[4] = {xv.x, xv.y, xv.z, xv.w};
#pragma unroll
        for (int s = 0; s < 4; s++) {
            unsigned char* const rb = (s & 1) ? bufB : bufA;   // read h
            unsigned char* const wb = (s & 1) ? bufA : bufB;   // write h'

            // ---- load 10 duplicated (h,h) pairs: 5x LDS.128 ----
            u64 hp[10];
#pragma unroll
            for (int q = 0; q < 5; q++) {
                ulonglong2 v = *reinterpret_cast<const ulonglong2*>(rb + 16 * q);
                hp[2 * q]     = v.x;
                hp[2 * q + 1] = v.y;
            }

            // ---- gates: tree-split packed matvec, zero pack-MOVs ----
            const float xt = xs[s];
            const u64 xpk = pack2(xt, xt);
            u64 a0if = ffma2(xpk, xif, bif);
            u64 a0go = ffma2(xpk, xgo, bgo);
            u64 a1if = fmul2(hp[0], wif[0]);
            u64 a1go = fmul2(hp[0], wgo[0]);
#pragma unroll
            for (int m = 1; m < 10; m++) {
                if (m & 1) {
                    a0if = ffma2(hp[m], wif[m], a0if);
                    a0go = ffma2(hp[m], wgo[m], a0go);
                } else {
                    a1if = ffma2(hp[m], wif[m], a1if);
                    a1go = ffma2(hp[m], wgo[m], a1go);
                }
            }

            // ---- pointwise (exponent-domain, 5 ex2 + 2 rcp) ----
            // A=e^-zi, F=e^-zf, B=e^-2zg, C=e^-zo
            // chat' = (chat*P + K2*(1-B)*Q) * rcp(Q*P), P=(1+A)(1+B), Q=1+F
            // D=2^chat';  h = (1-D)*rcp((1+C)(1+D))
            float ai, af, ag, ao;
            unpack2(fadd2(a0if, a1if), ai, af);
            unpack2(fadd2(a0go, a1go), ag, ao);
            const float A = ex2a(ai);
            const float F = ex2a(af);
            const float B = ex2a(ag);
            const float C = ex2a(ao);
            const float P  = (1.f + A) * (1.f + B);
            const float Q  = 1.f + F;
            const float kg = fmaf(B, -K2C, K2C);          // K2*(1-B)
            const float num = fmaf(chat, P, kg * Q);
            chat = num * rcpa(Q * P);
            const float D = ex2a(chat);
            const float hown = (1.f - D) * rcpa((1.f + C) * (1.f + D));

            // ---- publish duplicated pair, sync the warp ----
            *reinterpret_cast<u64*>(wb + 8 * row) = pack2(hown, hown);
            __syncwarp();
        }
    }

    // 256 steps: last write went to bufA (s=3 writes parity-0). Final sync done.
    if (valid && row == 0) {
        float acc = g_linb;
#pragma unroll
        for (int m = 0; m < 10; m++) {
            float hm = *reinterpret_cast<const float*>(bufA + 8 * m);
            acc = fmaf(hm, g_linw[m], acc);
        }
        out[elem] = acc;
    }
}

// ---------------- launch ----------------
extern "C" void kernel_launch(void* const* d_in, const int* in_sizes, int n_in,
                              void* d_out, int out_size)
{
    const float* x        = (const float*)d_in[0];
    const float* w_ih_mu  = (const float*)d_in[1];
    const float* w_ih_rho = (const float*)d_in[2];
    const float* w_hh_mu  = (const float*)d_in[3];
    const float* w_hh_rho = (const float*)d_in[4];
    const float* b_mu     = (const float*)d_in[5];
    const float* b_rho    = (const float*)d_in[6];
    const float* eps_ih   = (const float*)d_in[7];
    const float* eps_hh   = (const float*)d_in[8];
    const float* eps_b    = (const float*)d_in[9];
    const float* lin_w    = (const float*)d_in[10];
    const float* lin_b    = (const float*)d_in[11];
    float* out = (float*)d_out;

    sample_pack_kernel<<<1, 128>>>(w_ih_mu, w_ih_rho, w_hh_mu, w_hh_rho,
                                   b_mu, b_rho, eps_ih, eps_hh, eps_b,
                                   lin_w, lin_b);

    const int nblocks = (BATCH + 2) / 3;   // 2731 one-warp blocks
    lstm_fwd_kernel<<<nblocks, 32>>>(x, out);
}